// round 4
// baseline (speedup 1.0000x reference)
#include <cuda_runtime.h>
#include <math.h>
#include <float.h>

#define NN 50000
#define NE 800000
#define DD 128
#define BIGF 1000000000.0f

// ---------------- scratch (static device globals; no allocs) ----------------
__device__ float  g_z[NN * DD];      // z = h@W + b   (25.6 MB)
__device__ float  g_s[NN];           // z . w_src
__device__ float  g_t[NN];           // z . w_dst
__device__ float  g_hnew[NN * DD];   // aggregated output (25.6 MB)
__device__ float  g_colsum[DD];
__device__ float  g_colsq[DD];
__device__ int    g_cnt[NN];         // degree counts
__device__ int    g_off[NN + 1];     // CSR offsets
__device__ int    g_cursor[NN];      // fill cursors
__device__ float4 g_pack[NE];        // per CSR slot: {src(bits), e, sigma, -}

__device__ __forceinline__ float clamp_inf(float v) {
    return isinf(v) ? BIGF : v;
}
__device__ __forceinline__ float to_tf32(float x) {
    float r; asm("cvt.rna.tf32.f32 %0, %1;" : "=f"(r) : "f"(x)); return r;
}
__device__ __forceinline__ void mma_tf32(float* c, const float* a, const float* b) {
    asm volatile("mma.sync.aligned.m16n8k8.row.col.f32.tf32.tf32.f32 "
                 "{%0,%1,%2,%3}, {%4,%5,%6,%7}, {%8,%9}, {%0,%1,%2,%3};"
                 : "+f"(c[0]), "+f"(c[1]), "+f"(c[2]), "+f"(c[3])
                 : "r"(__float_as_uint(a[0])), "r"(__float_as_uint(a[1])),
                   "r"(__float_as_uint(a[2])), "r"(__float_as_uint(a[3])),
                   "r"(__float_as_uint(b[0])), "r"(__float_as_uint(b[1])));
}

// ---------------- kernel 0: init counters ----------------
__global__ void k_init() {
    int i = blockIdx.x * blockDim.x + threadIdx.x;
    if (i < NN) g_cnt[i] = 0;
    if (i < DD) { g_colsum[i] = 0.0f; g_colsq[i] = 0.0f; }
}

// ---------------- kernel 1: tf32x3 tensor-core GEMM + fused attn dots ----------------
// BM=128, BN=128, BK=16, 8 warps; warp tile 32x64 (2 m16 x 8 n8 mma tiles)
__global__ __launch_bounds__(256) void k_gemm_tc(const float* __restrict__ H,
                                                 const float* __restrict__ W,
                                                 const float* __restrict__ Bv,
                                                 const float* __restrict__ AW) {
    __shared__ float Ah[128][20], Al[128][20];    // A chunk hi/lo, padded
    __shared__ float Bh[16][136], Bl[16][136];    // W chunk hi/lo, padded
    __shared__ float s_sp[128][2], s_tp[128][2];  // cross-warp s/t partials

    const int tid = threadIdx.x;
    const int lane = tid & 31;
    const int wid = tid >> 5;
    const int gid = lane >> 2;       // 0..7
    const int tig = lane & 3;        // 0..3
    const int wr = wid & 3;          // warp row block (32 rows)
    const int wc = wid >> 2;         // warp col block (64 cols)
    const int row0 = blockIdx.x * 128;

    float c[2][8][4];
#pragma unroll
    for (int mt = 0; mt < 2; mt++)
#pragma unroll
        for (int nt = 0; nt < 8; nt++)
#pragma unroll
            for (int i = 0; i < 4; i++) c[mt][nt][i] = 0.0f;

    for (int k0 = 0; k0 < 128; k0 += 16) {
        __syncthreads();
        // load A chunk 128x16 (2 float4 per thread)
#pragma unroll
        for (int l = 0; l < 2; l++) {
            int idx = tid + l * 256;          // 0..511
            int row = idx >> 2;
            int cc = (idx & 3) * 4;
            float4 v = make_float4(0.f, 0.f, 0.f, 0.f);
            if (row0 + row < NN) v = *(const float4*)&H[(row0 + row) * 128 + k0 + cc];
            float hx = to_tf32(v.x), hy = to_tf32(v.y), hz = to_tf32(v.z), hw = to_tf32(v.w);
            Ah[row][cc + 0] = hx; Al[row][cc + 0] = to_tf32(v.x - hx);
            Ah[row][cc + 1] = hy; Al[row][cc + 1] = to_tf32(v.y - hy);
            Ah[row][cc + 2] = hz; Al[row][cc + 2] = to_tf32(v.z - hz);
            Ah[row][cc + 3] = hw; Al[row][cc + 3] = to_tf32(v.w - hw);
        }
        // load B chunk 16x128
#pragma unroll
        for (int l = 0; l < 2; l++) {
            int idx = tid + l * 256;
            int kr = idx >> 5;
            int cc = (idx & 31) * 4;
            float4 v = *(const float4*)&W[(k0 + kr) * 128 + cc];
            float hx = to_tf32(v.x), hy = to_tf32(v.y), hz = to_tf32(v.z), hw = to_tf32(v.w);
            Bh[kr][cc + 0] = hx; Bl[kr][cc + 0] = to_tf32(v.x - hx);
            Bh[kr][cc + 1] = hy; Bl[kr][cc + 1] = to_tf32(v.y - hy);
            Bh[kr][cc + 2] = hz; Bl[kr][cc + 2] = to_tf32(v.z - hz);
            Bh[kr][cc + 3] = hw; Bl[kr][cc + 3] = to_tf32(v.w - hw);
        }
        __syncthreads();

#pragma unroll
        for (int ks = 0; ks < 2; ks++) {
            const int kb = ks * 8;
            float ah[2][4], al[2][4];
#pragma unroll
            for (int mt = 0; mt < 2; mt++) {
                int rb = wr * 32 + mt * 16;
                ah[mt][0] = Ah[rb + gid][kb + tig];
                ah[mt][1] = Ah[rb + gid + 8][kb + tig];
                ah[mt][2] = Ah[rb + gid][kb + tig + 4];
                ah[mt][3] = Ah[rb + gid + 8][kb + tig + 4];
                al[mt][0] = Al[rb + gid][kb + tig];
                al[mt][1] = Al[rb + gid + 8][kb + tig];
                al[mt][2] = Al[rb + gid][kb + tig + 4];
                al[mt][3] = Al[rb + gid + 8][kb + tig + 4];
            }
#pragma unroll
            for (int nt = 0; nt < 8; nt++) {
                int cb = wc * 64 + nt * 8;
                float bh[2], bl[2];
                bh[0] = Bh[kb + tig][cb + gid];
                bh[1] = Bh[kb + tig + 4][cb + gid];
                bl[0] = Bl[kb + tig][cb + gid];
                bl[1] = Bl[kb + tig + 4][cb + gid];
#pragma unroll
                for (int mt = 0; mt < 2; mt++) {
                    mma_tf32(c[mt][nt], ah[mt], bh);   // hi*hi
                    mma_tf32(c[mt][nt], al[mt], bh);   // lo*hi
                    mma_tf32(c[mt][nt], ah[mt], bl);   // hi*lo
                }
            }
        }
    }

    // epilogue: bias + clamp + store z + fused attention dots
    float sp0[2] = {0.f, 0.f}, tp0[2] = {0.f, 0.f};
    float sp1[2] = {0.f, 0.f}, tp1[2] = {0.f, 0.f};
#pragma unroll
    for (int mt = 0; mt < 2; mt++) {
        int rl0 = wr * 32 + mt * 16 + gid;
        int gr0 = row0 + rl0, gr1 = gr0 + 8;
#pragma unroll
        for (int nt = 0; nt < 8; nt++) {
            int col = wc * 64 + nt * 8 + tig * 2;
            float2 bb = *(const float2*)&Bv[col];
            float2 ws2 = *(const float2*)&AW[col];
            float2 wd2 = *(const float2*)&AW[128 + col];
            float v0 = clamp_inf(c[mt][nt][0] + bb.x);
            float v1 = clamp_inf(c[mt][nt][1] + bb.y);
            float v2 = clamp_inf(c[mt][nt][2] + bb.x);
            float v3 = clamp_inf(c[mt][nt][3] + bb.y);
            if (gr0 < NN) *(float2*)&g_z[gr0 * 128 + col] = make_float2(v0, v1);
            if (gr1 < NN) *(float2*)&g_z[gr1 * 128 + col] = make_float2(v2, v3);
            sp0[mt] += v0 * ws2.x + v1 * ws2.y;
            tp0[mt] += v0 * wd2.x + v1 * wd2.y;
            sp1[mt] += v2 * ws2.x + v3 * ws2.y;
            tp1[mt] += v2 * wd2.x + v3 * wd2.y;
        }
    }
#pragma unroll
    for (int o = 1; o <= 2; o <<= 1) {
#pragma unroll
        for (int mt = 0; mt < 2; mt++) {
            sp0[mt] += __shfl_xor_sync(0xffffffffu, sp0[mt], o);
            tp0[mt] += __shfl_xor_sync(0xffffffffu, tp0[mt], o);
            sp1[mt] += __shfl_xor_sync(0xffffffffu, sp1[mt], o);
            tp1[mt] += __shfl_xor_sync(0xffffffffu, tp1[mt], o);
        }
    }
    if (tig == 0) {
#pragma unroll
        for (int mt = 0; mt < 2; mt++) {
            int rl = wr * 32 + mt * 16 + gid;
            s_sp[rl][wc] = sp0[mt];      s_tp[rl][wc] = tp0[mt];
            s_sp[rl + 8][wc] = sp1[mt];  s_tp[rl + 8][wc] = tp1[mt];
        }
    }
    __syncthreads();
    if (tid < 128) {
        int gr = row0 + tid;
        if (gr < NN) {
            g_s[gr] = s_sp[tid][0] + s_sp[tid][1];
            g_t[gr] = s_tp[tid][0] + s_tp[tid][1];
        }
    }
}

// ---------------- kernel 2: degree histogram ----------------
__global__ void k_hist(const int* __restrict__ dst) {
    int i = blockIdx.x * blockDim.x + threadIdx.x;
    if (i < NE) atomicAdd(&g_cnt[dst[i]], 1);
}

// ---------------- kernel 3: exclusive scan (single block) ----------------
__global__ __launch_bounds__(1024) void k_scan() {
    __shared__ int sums[1024];
    const int t = threadIdx.x;
    const int C = (NN + 1023) / 1024;   // 49
    int b = t * C;
    int e = min(b + C, NN);
    int s = 0;
    for (int i = b; i < e; i++) s += g_cnt[i];
    sums[t] = s;
    __syncthreads();
    for (int off = 1; off < 1024; off <<= 1) {
        int v = (t >= off) ? sums[t - off] : 0;
        __syncthreads();
        sums[t] += v;
        __syncthreads();
    }
    int running = sums[t] - s;   // exclusive base
    for (int i = b; i < e; i++) {
        g_off[i] = running;
        g_cursor[i] = running;
        running += g_cnt[i];
    }
    if (t == 1023) g_off[NN] = NE;
}

// ---------------- kernel 4: CSR fill with packed edge record ----------------
__global__ void k_fill(const int* __restrict__ src, const int* __restrict__ dst,
                       const float* __restrict__ sigma,
                       const float* __restrict__ attnb) {
    int i = blockIdx.x * blockDim.x + threadIdx.x;
    if (i >= NE) return;
    int d = dst[i];
    int s = src[i];
    float a = clamp_inf(g_s[s] + g_t[d] + attnb[0]);
    float e = (a > 0.0f) ? a : 0.01f * a;       // leaky relu
    int pos = atomicAdd(&g_cursor[d], 1);
    g_pack[pos] = make_float4(__int_as_float(s), e, sigma[i], 0.0f);
}

// ---------------- kernel 5: fused softmax + aggregate + BN stats ----------------
__global__ __launch_bounds__(256) void k_node() {
    __shared__ float s_sum[DD];
    __shared__ float s_sq[DD];
    const int tid = threadIdx.x;
    if (tid < DD) { s_sum[tid] = 0.0f; s_sq[tid] = 0.0f; }
    __syncthreads();

    const int lane = tid & 31;
    const int node = blockIdx.x * 8 + (tid >> 5);   // NN = 6250*8 exactly

    const int beg = g_off[node];
    const int end = g_off[node + 1];

    // phase A: warp max over e
    float m = -FLT_MAX;
    for (int j = beg + lane; j < end; j += 32)
        m = fmaxf(m, g_pack[j].y);
#pragma unroll
    for (int o = 16; o > 0; o >>= 1) m = fmaxf(m, __shfl_xor_sync(0xffffffffu, m, o));

    // phase B: denom + beta-sum
    float den = 0.0f, bs = 0.0f;
    for (int j = beg + lane; j < end; j += 32) {
        float4 p = g_pack[j];
        den += __expf(p.y - m);
        bs += p.z;
    }
#pragma unroll
    for (int o = 16; o > 0; o >>= 1) {
        den += __shfl_xor_sync(0xffffffffu, den, o);
        bs  += __shfl_xor_sync(0xffffffffu, bs, o);
    }
    float rc = (1.0f / den) * (1.0f / (bs + 1e-6f));

    // phase C: gather-accumulate, unroll 4 for MLP
    float4 a0 = make_float4(0.f, 0.f, 0.f, 0.f);
    float4 a1 = make_float4(0.f, 0.f, 0.f, 0.f);
    float4 a2 = make_float4(0.f, 0.f, 0.f, 0.f);
    float4 a3 = make_float4(0.f, 0.f, 0.f, 0.f);
    int j = beg;
    for (; j + 3 < end; j += 4) {
        float4 p0 = g_pack[j];
        float4 p1 = g_pack[j + 1];
        float4 p2 = g_pack[j + 2];
        float4 p3 = g_pack[j + 3];
        int s0 = __float_as_int(p0.x), s1 = __float_as_int(p1.x);
        int s2 = __float_as_int(p2.x), s3 = __float_as_int(p3.x);
        float4 z0 = *(const float4*)&g_z[s0 * DD + lane * 4];
        float4 z1 = *(const float4*)&g_z[s1 * DD + lane * 4];
        float4 z2 = *(const float4*)&g_z[s2 * DD + lane * 4];
        float4 z3 = *(const float4*)&g_z[s3 * DD + lane * 4];
        float c0 = __expf(p0.y - m) * p0.z * rc;
        float c1 = __expf(p1.y - m) * p1.z * rc;
        float c2 = __expf(p2.y - m) * p2.z * rc;
        float c3 = __expf(p3.y - m) * p3.z * rc;
        a0.x += c0 * z0.x; a0.y += c0 * z0.y; a0.z += c0 * z0.z; a0.w += c0 * z0.w;
        a1.x += c1 * z1.x; a1.y += c1 * z1.y; a1.z += c1 * z1.z; a1.w += c1 * z1.w;
        a2.x += c2 * z2.x; a2.y += c2 * z2.y; a2.z += c2 * z2.z; a2.w += c2 * z2.w;
        a3.x += c3 * z3.x; a3.y += c3 * z3.y; a3.z += c3 * z3.z; a3.w += c3 * z3.w;
    }
    for (; j < end; j++) {
        float4 p0 = g_pack[j];
        int s0 = __float_as_int(p0.x);
        float4 z0 = *(const float4*)&g_z[s0 * DD + lane * 4];
        float c0 = __expf(p0.y - m) * p0.z * rc;
        a0.x += c0 * z0.x; a0.y += c0 * z0.y; a0.z += c0 * z0.z; a0.w += c0 * z0.w;
    }
    float4 v;
    v.x = clamp_inf((a0.x + a1.x) + (a2.x + a3.x));
    v.y = clamp_inf((a0.y + a1.y) + (a2.y + a3.y));
    v.z = clamp_inf((a0.z + a1.z) + (a2.z + a3.z));
    v.w = clamp_inf((a0.w + a1.w) + (a2.w + a3.w));
    *(float4*)&g_hnew[node * DD + lane * 4] = v;

    int cc = lane * 4;
    atomicAdd(&s_sum[cc + 0], v.x); atomicAdd(&s_sq[cc + 0], v.x * v.x);
    atomicAdd(&s_sum[cc + 1], v.y); atomicAdd(&s_sq[cc + 1], v.y * v.y);
    atomicAdd(&s_sum[cc + 2], v.z); atomicAdd(&s_sq[cc + 2], v.z * v.z);
    atomicAdd(&s_sum[cc + 3], v.w); atomicAdd(&s_sq[cc + 3], v.w * v.w);

    __syncthreads();
    if (tid < DD) {
        atomicAdd(&g_colsum[tid], s_sum[tid]);
        atomicAdd(&g_colsq[tid], s_sq[tid]);
    }
}

// ---------------- kernel 6: batchnorm + elu ----------------
__global__ void k_bn(float* __restrict__ out, const float* __restrict__ gamma,
                     const float* __restrict__ beta) {
    int idx = blockIdx.x * blockDim.x + threadIdx.x;
    if (idx >= NN * DD) return;
    int c = idx & 127;
    const float inv_n = 1.0f / (float)NN;
    float mu = g_colsum[c] * inv_n;
    float var = g_colsq[c] * inv_n - mu * mu;
    float xb = (g_hnew[idx] - mu) * rsqrtf(var + 1e-5f) * gamma[c] + beta[c];
    out[idx] = (xb > 0.0f) ? xb : expm1f(xb);   // elu
}

// ---------------- launcher ----------------
extern "C" void kernel_launch(void* const* d_in, const int* in_sizes, int n_in,
                              void* d_out, int out_size) {
    const float* h     = (const float*)d_in[0];
    const int*   src   = (const int*)d_in[1];
    const int*   dst   = (const int*)d_in[2];
    const float* sigma = (const float*)d_in[3];
    const float* fcw   = (const float*)d_in[4];
    const float* fcb   = (const float*)d_in[5];
    const float* attnw = (const float*)d_in[6];
    const float* attnb = (const float*)d_in[7];
    const float* gamma = (const float*)d_in[8];
    const float* beta  = (const float*)d_in[9];
    float* out = (float*)d_out;

    k_init<<<(NN + 255) / 256, 256>>>();
    k_hist<<<(NE + 255) / 256, 256>>>(dst);
    k_scan<<<1, 1024>>>();
    k_gemm_tc<<<(NN + 127) / 128, 256>>>(h, fcw, fcb, attnw);
    k_fill<<<(NE + 255) / 256, 256>>>(src, dst, sigma, attnb);
    k_node<<<NN / 8, 256>>>();
    k_bn<<<(NN * DD + 255) / 256, 256>>>(out, gamma, beta);
}

// round 5
// speedup vs baseline: 1.1273x; 1.1273x over previous
#include <cuda_runtime.h>
#include <cuda_bf16.h>
#include <math.h>
#include <float.h>

#define NN 50000
#define NE 800000
#define DD 128
#define BIGF 1000000000.0f

// ---------------- scratch (static device globals; no allocs) ----------------
__device__ float g_z[NN * DD];      // z = h@W + b   (25.6 MB)
__device__ float g_s[NN];           // z . w_src
__device__ float g_t[NN];           // z . w_dst
__device__ float g_hnew[NN * DD];   // aggregated output (25.6 MB)
__device__ float g_colsum[DD];
__device__ float g_colsq[DD];
__device__ int   g_cnt[NN];         // degree counts
__device__ int   g_off[NN + 1];     // CSR offsets
__device__ int   g_cursor[NN];      // fill cursors
__device__ int2  g_pack[NE];        // per CSR slot: {src, sigma(bits)}

__device__ __forceinline__ float clamp_inf(float v) {
    return isinf(v) ? BIGF : v;
}

// ---------------- bf16 split helpers ----------------
__device__ __forceinline__ unsigned short bfb(float x) {
    __nv_bfloat16 b = __float2bfloat16(x);
    return *reinterpret_cast<unsigned short*>(&b);
}
__device__ __forceinline__ float bff(unsigned short u) {
    return __bfloat162float(*reinterpret_cast<__nv_bfloat16*>(&u));
}
// pack two consecutive-k values into bf16x2 hi word + lo (residual) word
__device__ __forceinline__ void pack_hl(float x0, float x1, unsigned& hi, unsigned& lo) {
    unsigned short h0 = bfb(x0);
    unsigned short h1 = bfb(x1);
    float r0 = x0 - bff(h0);
    float r1 = x1 - bff(h1);
    hi = ((unsigned)h1 << 16) | (unsigned)h0;
    lo = ((unsigned)bfb(r1) << 16) | (unsigned)bfb(r0);
}
__device__ __forceinline__ void mma_bf16(float* c, const unsigned* a, unsigned b0, unsigned b1) {
    asm volatile("mma.sync.aligned.m16n8k16.row.col.f32.bf16.bf16.f32 "
                 "{%0,%1,%2,%3}, {%4,%5,%6,%7}, {%8,%9}, {%0,%1,%2,%3};"
                 : "+f"(c[0]), "+f"(c[1]), "+f"(c[2]), "+f"(c[3])
                 : "r"(a[0]), "r"(a[1]), "r"(a[2]), "r"(a[3]), "r"(b0), "r"(b1));
}

// ---------------- kernel 0: init counters ----------------
__global__ void k_init() {
    int i = blockIdx.x * blockDim.x + threadIdx.x;
    if (i < NN) g_cnt[i] = 0;
    if (i < DD) { g_colsum[i] = 0.0f; g_colsq[i] = 0.0f; }
}

// ---------------- kernel 1: bf16x3 tensor GEMM + fused attn dots ----------------
// BM=128, BN=128, BK=16; 8 warps, warp tile 32x64 (2 m16 x 8 n8 tiles)
#define NKP 12   // padded k-pair stride (words) for conflict-free fragment loads
__global__ __launch_bounds__(256) void k_gemm_bf(const float* __restrict__ H,
                                                 const float* __restrict__ W,
                                                 const float* __restrict__ Bv,
                                                 const float* __restrict__ AW) {
    __shared__ unsigned Ah[128 * NKP], Al[128 * NKP];   // A rows x kpairs
    __shared__ unsigned Bh[128 * NKP], Bl[128 * NKP];   // B cols x kpairs
    __shared__ float s_sp[128][2], s_tp[128][2];

    const int tid = threadIdx.x;
    const int lane = tid & 31;
    const int wid = tid >> 5;
    const int g = lane >> 2;      // 0..7
    const int t = lane & 3;       // 0..3
    const int wr = wid & 3;       // warp row block (32 rows)
    const int wc = wid >> 2;      // warp col block (64 cols)
    const int row0 = blockIdx.x * 128;

    float c[2][8][4];
#pragma unroll
    for (int mt = 0; mt < 2; mt++)
#pragma unroll
        for (int nt = 0; nt < 8; nt++)
#pragma unroll
            for (int i = 0; i < 4; i++) c[mt][nt][i] = 0.0f;

    for (int k0 = 0; k0 < 128; k0 += 16) {
        __syncthreads();
        // A conversion: 128 rows x 16 k
#pragma unroll
        for (int l = 0; l < 2; l++) {
            int f = tid + l * 256;            // 0..511
            int row = f >> 2;                 // 0..127
            int cc = (f & 3) * 4;             // k offset 0,4,8,12
            float4 v = make_float4(0.f, 0.f, 0.f, 0.f);
            if (row0 + row < NN) v = *(const float4*)&H[(row0 + row) * 128 + k0 + cc];
            unsigned h0, l0, h1, l1;
            pack_hl(v.x, v.y, h0, l0);
            pack_hl(v.z, v.w, h1, l1);
            int base = row * NKP + (cc >> 1);
            Ah[base] = h0;     Al[base] = l0;
            Ah[base + 1] = h1; Al[base + 1] = l1;
        }
        // B conversion (transpose W[k][n] -> Bpk[col][kpair])
        {
            int cg = tid >> 3;                // 0..31 -> cols cg*4..+3
            int kp = tid & 7;                 // kpair 0..7
            int krow = k0 + kp * 2;
            float4 v0 = *(const float4*)&W[krow * 128 + cg * 4];
            float4 v1 = *(const float4*)&W[(krow + 1) * 128 + cg * 4];
            float a0[4] = {v0.x, v0.y, v0.z, v0.w};
            float a1[4] = {v1.x, v1.y, v1.z, v1.w};
#pragma unroll
            for (int i = 0; i < 4; i++) {
                unsigned hh, ll;
                pack_hl(a0[i], a1[i], hh, ll);
                int col = cg * 4 + i;
                Bh[col * NKP + kp] = hh;
                Bl[col * NKP + kp] = ll;
            }
        }
        __syncthreads();

        // fragment loads + mma
        unsigned ah[2][4], alr[2][4];
#pragma unroll
        for (int mt = 0; mt < 2; mt++) {
            int rb = wr * 32 + mt * 16;
            int b0i = (rb + g) * NKP + t;
            int b1i = (rb + g + 8) * NKP + t;
            ah[mt][0] = Ah[b0i];      ah[mt][1] = Ah[b1i];
            ah[mt][2] = Ah[b0i + 4];  ah[mt][3] = Ah[b1i + 4];
            alr[mt][0] = Al[b0i];     alr[mt][1] = Al[b1i];
            alr[mt][2] = Al[b0i + 4]; alr[mt][3] = Al[b1i + 4];
        }
#pragma unroll
        for (int nt = 0; nt < 8; nt++) {
            int col = wc * 64 + nt * 8 + g;
            unsigned bh0 = Bh[col * NKP + t], bh1 = Bh[col * NKP + t + 4];
            unsigned bl0 = Bl[col * NKP + t], bl1 = Bl[col * NKP + t + 4];
#pragma unroll
            for (int mt = 0; mt < 2; mt++) {
                mma_bf16(c[mt][nt], ah[mt], bh0, bh1);    // hi*hi
                mma_bf16(c[mt][nt], alr[mt], bh0, bh1);   // lo*hi
                mma_bf16(c[mt][nt], ah[mt], bl0, bl1);    // hi*lo
            }
        }
    }

    // epilogue: bias + clamp + store z + fused attention dots
    float sp0[2] = {0.f, 0.f}, tp0[2] = {0.f, 0.f};
    float sp1[2] = {0.f, 0.f}, tp1[2] = {0.f, 0.f};
#pragma unroll
    for (int mt = 0; mt < 2; mt++) {
        int rl0 = wr * 32 + mt * 16 + g;
        int gr0 = row0 + rl0, gr1 = gr0 + 8;
#pragma unroll
        for (int nt = 0; nt < 8; nt++) {
            int col = wc * 64 + nt * 8 + t * 2;
            float2 bb = *(const float2*)&Bv[col];
            float2 ws2 = *(const float2*)&AW[col];
            float2 wd2 = *(const float2*)&AW[128 + col];
            float v0 = clamp_inf(c[mt][nt][0] + bb.x);
            float v1 = clamp_inf(c[mt][nt][1] + bb.y);
            float v2 = clamp_inf(c[mt][nt][2] + bb.x);
            float v3 = clamp_inf(c[mt][nt][3] + bb.y);
            if (gr0 < NN) *(float2*)&g_z[gr0 * 128 + col] = make_float2(v0, v1);
            if (gr1 < NN) *(float2*)&g_z[gr1 * 128 + col] = make_float2(v2, v3);
            sp0[mt] += v0 * ws2.x + v1 * ws2.y;
            tp0[mt] += v0 * wd2.x + v1 * wd2.y;
            sp1[mt] += v2 * ws2.x + v3 * ws2.y;
            tp1[mt] += v2 * wd2.x + v3 * wd2.y;
        }
    }
#pragma unroll
    for (int o = 1; o <= 2; o <<= 1) {
#pragma unroll
        for (int mt = 0; mt < 2; mt++) {
            sp0[mt] += __shfl_xor_sync(0xffffffffu, sp0[mt], o);
            tp0[mt] += __shfl_xor_sync(0xffffffffu, tp0[mt], o);
            sp1[mt] += __shfl_xor_sync(0xffffffffu, sp1[mt], o);
            tp1[mt] += __shfl_xor_sync(0xffffffffu, tp1[mt], o);
        }
    }
    if (t == 0) {
#pragma unroll
        for (int mt = 0; mt < 2; mt++) {
            int rl = wr * 32 + mt * 16 + g;
            s_sp[rl][wc] = sp0[mt];      s_tp[rl][wc] = tp0[mt];
            s_sp[rl + 8][wc] = sp1[mt];  s_tp[rl + 8][wc] = tp1[mt];
        }
    }
    __syncthreads();
    if (tid < 128) {
        int gr = row0 + tid;
        if (gr < NN) {
            g_s[gr] = s_sp[tid][0] + s_sp[tid][1];
            g_t[gr] = s_tp[tid][0] + s_tp[tid][1];
        }
    }
}

// ---------------- kernel 2: degree histogram (4 edges/thread) ----------------
__global__ void k_hist(const int* __restrict__ dst) {
    int i = (blockIdx.x * blockDim.x + threadIdx.x) * 4;
    if (i >= NE) return;
    int4 d4 = *(const int4*)&dst[i];
    atomicAdd(&g_cnt[d4.x], 1);
    atomicAdd(&g_cnt[d4.y], 1);
    atomicAdd(&g_cnt[d4.z], 1);
    atomicAdd(&g_cnt[d4.w], 1);
}

// ---------------- kernel 3: exclusive scan (single block) ----------------
__global__ __launch_bounds__(1024) void k_scan() {
    __shared__ int sums[1024];
    const int t = threadIdx.x;
    const int C = (NN + 1023) / 1024;
    int b = t * C;
    int e = min(b + C, NN);
    int s = 0;
    for (int i = b; i < e; i++) s += g_cnt[i];
    sums[t] = s;
    __syncthreads();
    for (int off = 1; off < 1024; off <<= 1) {
        int v = (t >= off) ? sums[t - off] : 0;
        __syncthreads();
        sums[t] += v;
        __syncthreads();
    }
    int running = sums[t] - s;
    for (int i = b; i < e; i++) {
        g_off[i] = running;
        g_cursor[i] = running;
        running += g_cnt[i];
    }
    if (t == 1023) g_off[NN] = NE;
}

// ---------------- kernel 4: thin CSR fill {src, sigma} (no gemm dependence) ----------------
__global__ void k_fill(const int* __restrict__ src, const int* __restrict__ dst,
                       const float* __restrict__ sigma) {
    int i = (blockIdx.x * blockDim.x + threadIdx.x) * 4;
    if (i >= NE) return;
    int4 s4 = *(const int4*)&src[i];
    int4 d4 = *(const int4*)&dst[i];
    float4 g4 = *(const float4*)&sigma[i];
    int p;
    p = atomicAdd(&g_cursor[d4.x], 1); g_pack[p] = make_int2(s4.x, __float_as_int(g4.x));
    p = atomicAdd(&g_cursor[d4.y], 1); g_pack[p] = make_int2(s4.y, __float_as_int(g4.y));
    p = atomicAdd(&g_cursor[d4.z], 1); g_pack[p] = make_int2(s4.z, __float_as_int(g4.z));
    p = atomicAdd(&g_cursor[d4.w], 1); g_pack[p] = make_int2(s4.w, __float_as_int(g4.w));
}

// ---------------- kernel 5: fused softmax + aggregate + BN stats ----------------
// one warp per node; logits recomputed from L1-resident g_s
__global__ __launch_bounds__(256) void k_node(const float* __restrict__ attnb) {
    __shared__ float s_sum[DD];
    __shared__ float s_sq[DD];
    const int tid = threadIdx.x;
    if (tid < DD) { s_sum[tid] = 0.0f; s_sq[tid] = 0.0f; }
    __syncthreads();

    const int lane = tid & 31;
    const int node = blockIdx.x * 8 + (tid >> 5);   // NN = 6250*8 exactly

    const int beg = g_off[node];
    const int end = g_off[node + 1];
    const float tb = g_t[node] + attnb[0];

    // phase A: logits + warp max
    float m = -FLT_MAX;
    for (int j = beg + lane; j < end; j += 32) {
        int2 p = g_pack[j];
        float a = clamp_inf(g_s[p.x] + tb);
        float e = (a > 0.0f) ? a : 0.01f * a;
        m = fmaxf(m, e);
    }
#pragma unroll
    for (int o = 16; o > 0; o >>= 1) m = fmaxf(m, __shfl_xor_sync(0xffffffffu, m, o));

    // phase B: denom + beta-sum (g_s now L1-hit)
    float den = 0.0f, bs = 0.0f;
    for (int j = beg + lane; j < end; j += 32) {
        int2 p = g_pack[j];
        float a = clamp_inf(g_s[p.x] + tb);
        float e = (a > 0.0f) ? a : 0.01f * a;
        den += __expf(e - m);
        bs += __int_as_float(p.y);
    }
#pragma unroll
    for (int o = 16; o > 0; o >>= 1) {
        den += __shfl_xor_sync(0xffffffffu, den, o);
        bs  += __shfl_xor_sync(0xffffffffu, bs, o);
    }
    float rc = (1.0f / den) * (1.0f / (bs + 1e-6f));

    // phase C: gather-accumulate, unroll 4 for MLP
    float4 a0 = make_float4(0.f, 0.f, 0.f, 0.f);
    float4 a1 = make_float4(0.f, 0.f, 0.f, 0.f);
    float4 a2 = make_float4(0.f, 0.f, 0.f, 0.f);
    float4 a3 = make_float4(0.f, 0.f, 0.f, 0.f);
    int j = beg;
    for (; j + 3 < end; j += 4) {
        int2 p0 = g_pack[j],     p1 = g_pack[j + 1];
        int2 p2 = g_pack[j + 2], p3 = g_pack[j + 3];
        float4 z0 = *(const float4*)&g_z[p0.x * DD + lane * 4];
        float4 z1 = *(const float4*)&g_z[p1.x * DD + lane * 4];
        float4 z2 = *(const float4*)&g_z[p2.x * DD + lane * 4];
        float4 z3 = *(const float4*)&g_z[p3.x * DD + lane * 4];
        float e0, e1, e2, e3, aa;
        aa = clamp_inf(g_s[p0.x] + tb); e0 = (aa > 0.f) ? aa : 0.01f * aa;
        aa = clamp_inf(g_s[p1.x] + tb); e1 = (aa > 0.f) ? aa : 0.01f * aa;
        aa = clamp_inf(g_s[p2.x] + tb); e2 = (aa > 0.f) ? aa : 0.01f * aa;
        aa = clamp_inf(g_s[p3.x] + tb); e3 = (aa > 0.f) ? aa : 0.01f * aa;
        float c0 = __expf(e0 - m) * __int_as_float(p0.y) * rc;
        float c1 = __expf(e1 - m) * __int_as_float(p1.y) * rc;
        float c2 = __expf(e2 - m) * __int_as_float(p2.y) * rc;
        float c3 = __expf(e3 - m) * __int_as_float(p3.y) * rc;
        a0.x += c0 * z0.x; a0.y += c0 * z0.y; a0.z += c0 * z0.z; a0.w += c0 * z0.w;
        a1.x += c1 * z1.x; a1.y += c1 * z1.y; a1.z += c1 * z1.z; a1.w += c1 * z1.w;
        a2.x += c2 * z2.x; a2.y += c2 * z2.y; a2.z += c2 * z2.z; a2.w += c2 * z2.w;
        a3.x += c3 * z3.x; a3.y += c3 * z3.y; a3.z += c3 * z3.z; a3.w += c3 * z3.w;
    }
    for (; j < end; j++) {
        int2 p0 = g_pack[j];
        float4 z0 = *(const float4*)&g_z[p0.x * DD + lane * 4];
        float aa = clamp_inf(g_s[p0.x] + tb);
        float e0 = (aa > 0.f) ? aa : 0.01f * aa;
        float c0 = __expf(e0 - m) * __int_as_float(p0.y) * rc;
        a0.x += c0 * z0.x; a0.y += c0 * z0.y; a0.z += c0 * z0.z; a0.w += c0 * z0.w;
    }
    float4 v;
    v.x = clamp_inf((a0.x + a1.x) + (a2.x + a3.x));
    v.y = clamp_inf((a0.y + a1.y) + (a2.y + a3.y));
    v.z = clamp_inf((a0.z + a1.z) + (a2.z + a3.z));
    v.w = clamp_inf((a0.w + a1.w) + (a2.w + a3.w));
    *(float4*)&g_hnew[node * DD + lane * 4] = v;

    int cc = lane * 4;
    atomicAdd(&s_sum[cc + 0], v.x); atomicAdd(&s_sq[cc + 0], v.x * v.x);
    atomicAdd(&s_sum[cc + 1], v.y); atomicAdd(&s_sq[cc + 1], v.y * v.y);
    atomicAdd(&s_sum[cc + 2], v.z); atomicAdd(&s_sq[cc + 2], v.z * v.z);
    atomicAdd(&s_sum[cc + 3], v.w); atomicAdd(&s_sq[cc + 3], v.w * v.w);

    __syncthreads();
    if (tid < DD) {
        atomicAdd(&g_colsum[tid], s_sum[tid]);
        atomicAdd(&g_colsq[tid], s_sq[tid]);
    }
}

// ---------------- kernel 6: batchnorm + elu (vectorized) ----------------
__global__ void k_bn(float* __restrict__ out, const float* __restrict__ gamma,
                     const float* __restrict__ beta) {
    int i = blockIdx.x * blockDim.x + threadIdx.x;   // float4 index
    if (i >= NN * DD / 4) return;
    int c = (i & 31) * 4;
    const float inv_n = 1.0f / (float)NN;
    float4 cs = *(float4*)&g_colsum[c];
    float4 cq = *(float4*)&g_colsq[c];
    float4 gm = *(const float4*)&gamma[c];
    float4 bt = *(const float4*)&beta[c];
    float4 hv = *(float4*)&g_hnew[i * 4];
    float mu, var, xb;
    float4 o;
    mu = cs.x * inv_n; var = cq.x * inv_n - mu * mu;
    xb = (hv.x - mu) * rsqrtf(var + 1e-5f) * gm.x + bt.x;
    o.x = (xb > 0.0f) ? xb : expm1f(xb);
    mu = cs.y * inv_n; var = cq.y * inv_n - mu * mu;
    xb = (hv.y - mu) * rsqrtf(var + 1e-5f) * gm.y + bt.y;
    o.y = (xb > 0.0f) ? xb : expm1f(xb);
    mu = cs.z * inv_n; var = cq.z * inv_n - mu * mu;
    xb = (hv.z - mu) * rsqrtf(var + 1e-5f) * gm.z + bt.z;
    o.z = (xb > 0.0f) ? xb : expm1f(xb);
    mu = cs.w * inv_n; var = cq.w * inv_n - mu * mu;
    xb = (hv.w - mu) * rsqrtf(var + 1e-5f) * gm.w + bt.w;
    o.w = (xb > 0.0f) ? xb : expm1f(xb);
    *(float4*)&out[i * 4] = o;
}

// ---------------- launcher with fork/join overlap ----------------
extern "C" void kernel_launch(void* const* d_in, const int* in_sizes, int n_in,
                              void* d_out, int out_size) {
    const float* h     = (const float*)d_in[0];
    const int*   src   = (const int*)d_in[1];
    const int*   dst   = (const int*)d_in[2];
    const float* sigma = (const float*)d_in[3];
    const float* fcw   = (const float*)d_in[4];
    const float* fcb   = (const float*)d_in[5];
    const float* attnw = (const float*)d_in[6];
    const float* attnb = (const float*)d_in[7];
    const float* gamma = (const float*)d_in[8];
    const float* beta  = (const float*)d_in[9];
    float* out = (float*)d_out;

    // one-time side stream + events (no device memory involved)
    static cudaStream_t s2 = nullptr;
    static cudaEvent_t ev_fork = nullptr, ev_join = nullptr;
    if (s2 == nullptr) {
        cudaStreamCreate(&s2);
        cudaEventCreateWithFlags(&ev_fork, cudaEventDisableTiming);
        cudaEventCreateWithFlags(&ev_join, cudaEventDisableTiming);
    }

    // fork: CSR build on side stream, GEMM on main stream
    cudaEventRecord(ev_fork, 0);
    cudaStreamWaitEvent(s2, ev_fork, 0);
    k_init<<<(NN + 255) / 256, 256, 0, s2>>>();
    k_hist<<<(NE / 4 + 255) / 256, 256, 0, s2>>>(dst);
    k_scan<<<1, 1024, 0, s2>>>();
    k_fill<<<(NE / 4 + 255) / 256, 256, 0, s2>>>(src, dst, sigma);
    cudaEventRecord(ev_join, s2);

    k_gemm_bf<<<(NN + 127) / 128, 256>>>(h, fcw, fcb, attnw);

    // join
    cudaStreamWaitEvent(0, ev_join, 0);
    k_node<<<NN / 8, 256>>>(attnb);
    k_bn<<<(NN * DD / 4 + 255) / 256, 256>>>(out, gamma, beta);
}

// round 6
// speedup vs baseline: 1.2634x; 1.1207x over previous
#include <cuda_runtime.h>
#include <cuda_bf16.h>
#include <math.h>
#include <float.h>

#define NN 50000
#define NE 800000
#define DD 128
#define BIGF 1000000000.0f

// ---------------- scratch (static device globals; no allocs) ----------------
__device__ float    g_z[NN * DD];       // z = h@W + b   (25.6 MB)
__device__ float    g_s[NN];            // z . w_src
__device__ float    g_t[NN];            // z . w_dst
__device__ float    g_hnew[NN * DD];    // aggregated output (25.6 MB)
__device__ float    g_colsum[DD];
__device__ float    g_colsq[DD];
__device__ int      g_cnt[NN];          // degree counts
__device__ int      g_off[NN + 1];      // CSR offsets
__device__ int      g_cursor[NN];       // fill cursors
__device__ int2     g_pack[NE];         // per CSR slot: {src, sigma(bits)}
__device__ unsigned g_hh[NN * 64];      // H hi bf16x2 words (12.8 MB)
__device__ unsigned g_hl[NN * 64];      // H lo bf16x2 words (12.8 MB)
__device__ unsigned g_wh[128 * 64];     // W^T hi: [col][kpair]
__device__ unsigned g_wl[128 * 64];     // W^T lo

__device__ __forceinline__ float clamp_inf(float v) {
    return isinf(v) ? BIGF : v;
}
__device__ __forceinline__ unsigned short bfb(float x) {
    __nv_bfloat16 b = __float2bfloat16(x);
    return *reinterpret_cast<unsigned short*>(&b);
}
__device__ __forceinline__ float bff(unsigned short u) {
    return __bfloat162float(*reinterpret_cast<__nv_bfloat16*>(&u));
}
__device__ __forceinline__ void pack_hl(float x0, float x1, unsigned& hi, unsigned& lo) {
    unsigned short h0 = bfb(x0);
    unsigned short h1 = bfb(x1);
    float r0 = x0 - bff(h0);
    float r1 = x1 - bff(h1);
    hi = ((unsigned)h1 << 16) | (unsigned)h0;
    lo = ((unsigned)bfb(r1) << 16) | (unsigned)bfb(r0);
}
__device__ __forceinline__ void mma_bf16(float* c, const unsigned* a, unsigned b0, unsigned b1) {
    asm volatile("mma.sync.aligned.m16n8k16.row.col.f32.bf16.bf16.f32 "
                 "{%0,%1,%2,%3}, {%4,%5,%6,%7}, {%8,%9}, {%0,%1,%2,%3};"
                 : "+f"(c[0]), "+f"(c[1]), "+f"(c[2]), "+f"(c[3])
                 : "r"(a[0]), "r"(a[1]), "r"(a[2]), "r"(a[3]), "r"(b0), "r"(b1));
}

// ---------------- kernel 0: init counters ----------------
__global__ void k_init() {
    int i = blockIdx.x * blockDim.x + threadIdx.x;
    if (i < NN) g_cnt[i] = 0;
    if (i < DD) { g_colsum[i] = 0.0f; g_colsq[i] = 0.0f; }
}

// ---------------- prep: split H into bf16 hi/lo packed words ----------------
__global__ void k_prep(const float* __restrict__ H) {
    int i = blockIdx.x * blockDim.x + threadIdx.x;   // word index
    if (i >= NN * 64) return;
    float2 v = *(const float2*)&H[i * 2];
    unsigned hi, lo;
    pack_hl(v.x, v.y, hi, lo);
    g_hh[i] = hi;
    g_hl[i] = lo;
}

// ---------------- prep: transpose+split W into [col][kpair] ----------------
__global__ void k_prepw(const float* __restrict__ W) {
    int i = blockIdx.x * blockDim.x + threadIdx.x;   // 8192 words
    if (i >= 128 * 64) return;
    int col = i >> 6;
    int kp = i & 63;
    float x0 = W[(2 * kp) * 128 + col];
    float x1 = W[(2 * kp + 1) * 128 + col];
    unsigned hi, lo;
    pack_hl(x0, x1, hi, lo);
    g_wh[i] = hi;
    g_wl[i] = lo;
}

// ---------------- kernel 1: bf16x3 tensor GEMM + fused attn dots ----------------
// BM=128, BN=128, BK=16; 8 warps, warp tile 32x64 (2 m16 x 8 n8 tiles)
#define NKP 12   // padded k-pair stride (words): conflict-free fragment loads
__global__ __launch_bounds__(256) void k_gemm_bf(const float* __restrict__ Bv,
                                                 const float* __restrict__ AW) {
    __shared__ unsigned Ah[128 * NKP], Al[128 * NKP];
    __shared__ unsigned Bh[128 * NKP], Bl[128 * NKP];
    __shared__ float s_sp[128][2], s_tp[128][2];

    const int tid = threadIdx.x;
    const int lane = tid & 31;
    const int wid = tid >> 5;
    const int g = lane >> 2;
    const int t = lane & 3;
    const int wr = wid & 3;
    const int wc = wid >> 2;
    const int row0 = blockIdx.x * 128;

    float c[2][8][4];
#pragma unroll
    for (int mt = 0; mt < 2; mt++)
#pragma unroll
        for (int nt = 0; nt < 8; nt++)
#pragma unroll
            for (int i = 0; i < 4; i++) c[mt][nt][i] = 0.0f;

    for (int kc = 0; kc < 64; kc += 8) {      // kpair chunk (16 k per chunk)
        __syncthreads();
        // copy A chunk: 1024 words hi + lo
#pragma unroll
        for (int l = 0; l < 4; l++) {
            int i = tid + l * 256;            // 0..1023
            int row = i >> 3;
            int kp = i & 7;
            int gr = row0 + row;
            unsigned hv = 0, lv = 0;
            if (gr < NN) {
                hv = g_hh[gr * 64 + kc + kp];
                lv = g_hl[gr * 64 + kc + kp];
            }
            Ah[row * NKP + kp] = hv;
            Al[row * NKP + kp] = lv;
        }
        // copy B chunk
#pragma unroll
        for (int l = 0; l < 4; l++) {
            int i = tid + l * 256;
            int col = i >> 3;
            int kp = i & 7;
            Bh[col * NKP + kp] = g_wh[col * 64 + kc + kp];
            Bl[col * NKP + kp] = g_wl[col * 64 + kc + kp];
        }
        __syncthreads();

        unsigned ah[2][4], alr[2][4];
#pragma unroll
        for (int mt = 0; mt < 2; mt++) {
            int rb = wr * 32 + mt * 16;
            int b0i = (rb + g) * NKP + t;
            int b1i = (rb + g + 8) * NKP + t;
            ah[mt][0] = Ah[b0i];      ah[mt][1] = Ah[b1i];
            ah[mt][2] = Ah[b0i + 4];  ah[mt][3] = Ah[b1i + 4];
            alr[mt][0] = Al[b0i];     alr[mt][1] = Al[b1i];
            alr[mt][2] = Al[b0i + 4]; alr[mt][3] = Al[b1i + 4];
        }
#pragma unroll
        for (int nt = 0; nt < 8; nt++) {
            int col = wc * 64 + nt * 8 + g;
            unsigned bh0 = Bh[col * NKP + t], bh1 = Bh[col * NKP + t + 4];
            unsigned bl0 = Bl[col * NKP + t], bl1 = Bl[col * NKP + t + 4];
#pragma unroll
            for (int mt = 0; mt < 2; mt++) {
                mma_bf16(c[mt][nt], ah[mt], bh0, bh1);    // hi*hi
                mma_bf16(c[mt][nt], alr[mt], bh0, bh1);   // lo*hi
                mma_bf16(c[mt][nt], ah[mt], bl0, bl1);    // hi*lo
            }
        }
    }

    // epilogue: bias + clamp + store z + fused attention dots
    float sp0[2] = {0.f, 0.f}, tp0[2] = {0.f, 0.f};
    float sp1[2] = {0.f, 0.f}, tp1[2] = {0.f, 0.f};
#pragma unroll
    for (int mt = 0; mt < 2; mt++) {
        int rl0 = wr * 32 + mt * 16 + g;
        int gr0 = row0 + rl0, gr1 = gr0 + 8;
#pragma unroll
        for (int nt = 0; nt < 8; nt++) {
            int col = wc * 64 + nt * 8 + t * 2;
            float2 bb = *(const float2*)&Bv[col];
            float2 ws2 = *(const float2*)&AW[col];
            float2 wd2 = *(const float2*)&AW[128 + col];
            float v0 = clamp_inf(c[mt][nt][0] + bb.x);
            float v1 = clamp_inf(c[mt][nt][1] + bb.y);
            float v2 = clamp_inf(c[mt][nt][2] + bb.x);
            float v3 = clamp_inf(c[mt][nt][3] + bb.y);
            if (gr0 < NN) *(float2*)&g_z[gr0 * 128 + col] = make_float2(v0, v1);
            if (gr1 < NN) *(float2*)&g_z[gr1 * 128 + col] = make_float2(v2, v3);
            sp0[mt] += v0 * ws2.x + v1 * ws2.y;
            tp0[mt] += v0 * wd2.x + v1 * wd2.y;
            sp1[mt] += v2 * ws2.x + v3 * ws2.y;
            tp1[mt] += v2 * wd2.x + v3 * wd2.y;
        }
    }
#pragma unroll
    for (int o = 1; o <= 2; o <<= 1) {
#pragma unroll
        for (int mt = 0; mt < 2; mt++) {
            sp0[mt] += __shfl_xor_sync(0xffffffffu, sp0[mt], o);
            tp0[mt] += __shfl_xor_sync(0xffffffffu, tp0[mt], o);
            sp1[mt] += __shfl_xor_sync(0xffffffffu, sp1[mt], o);
            tp1[mt] += __shfl_xor_sync(0xffffffffu, tp1[mt], o);
        }
    }
    if (t == 0) {
#pragma unroll
        for (int mt = 0; mt < 2; mt++) {
            int rl = wr * 32 + mt * 16 + g;
            s_sp[rl][wc] = sp0[mt];      s_tp[rl][wc] = tp0[mt];
            s_sp[rl + 8][wc] = sp1[mt];  s_tp[rl + 8][wc] = tp1[mt];
        }
    }
    __syncthreads();
    if (tid < 128) {
        int gr = row0 + tid;
        if (gr < NN) {
            g_s[gr] = s_sp[tid][0] + s_sp[tid][1];
            g_t[gr] = s_tp[tid][0] + s_tp[tid][1];
        }
    }
}

// ---------------- kernel 2: degree histogram (4 edges/thread) ----------------
__global__ void k_hist(const int* __restrict__ dst) {
    int i = (blockIdx.x * blockDim.x + threadIdx.x) * 4;
    if (i >= NE) return;
    int4 d4 = *(const int4*)&dst[i];
    atomicAdd(&g_cnt[d4.x], 1);
    atomicAdd(&g_cnt[d4.y], 1);
    atomicAdd(&g_cnt[d4.z], 1);
    atomicAdd(&g_cnt[d4.w], 1);
}

// ---------------- kernel 3: exclusive scan (single block) ----------------
__global__ __launch_bounds__(1024) void k_scan() {
    __shared__ int sums[1024];
    const int t = threadIdx.x;
    const int C = (NN + 1023) / 1024;
    int b = t * C;
    int e = min(b + C, NN);
    int s = 0;
    for (int i = b; i < e; i++) s += g_cnt[i];
    sums[t] = s;
    __syncthreads();
    for (int off = 1; off < 1024; off <<= 1) {
        int v = (t >= off) ? sums[t - off] : 0;
        __syncthreads();
        sums[t] += v;
        __syncthreads();
    }
    int running = sums[t] - s;
    for (int i = b; i < e; i++) {
        g_off[i] = running;
        g_cursor[i] = running;
        running += g_cnt[i];
    }
    if (t == 1023) g_off[NN] = NE;
}

// ---------------- kernel 4: thin CSR fill {src, sigma} ----------------
__global__ void k_fill(const int* __restrict__ src, const int* __restrict__ dst,
                       const float* __restrict__ sigma) {
    int i = (blockIdx.x * blockDim.x + threadIdx.x) * 4;
    if (i >= NE) return;
    int4 s4 = *(const int4*)&src[i];
    int4 d4 = *(const int4*)&dst[i];
    float4 g4 = *(const float4*)&sigma[i];
    int p;
    p = atomicAdd(&g_cursor[d4.x], 1); g_pack[p] = make_int2(s4.x, __float_as_int(g4.x));
    p = atomicAdd(&g_cursor[d4.y], 1); g_pack[p] = make_int2(s4.y, __float_as_int(g4.y));
    p = atomicAdd(&g_cursor[d4.z], 1); g_pack[p] = make_int2(s4.z, __float_as_int(g4.z));
    p = atomicAdd(&g_cursor[d4.w], 1); g_pack[p] = make_int2(s4.w, __float_as_int(g4.w));
}

// ---------------- kernel 5: one-pass online softmax + aggregate + BN stats ----------------
// one warp per node; warp-uniform loop, all lanes track m/den/bsum redundantly
__global__ __launch_bounds__(256) void k_node(const float* __restrict__ attnb) {
    __shared__ float s_sum[DD];
    __shared__ float s_sq[DD];
    const int tid = threadIdx.x;
    if (tid < DD) { s_sum[tid] = 0.0f; s_sq[tid] = 0.0f; }
    __syncthreads();

    const int lane = tid & 31;
    const int node = blockIdx.x * 8 + (tid >> 5);   // NN = 6250*8 exactly

    const int beg = g_off[node];
    const int end = g_off[node + 1];
    const float tb = g_t[node] + attnb[0];
    const int co = lane * 4;                        // this lane's 4 columns

    float m = -FLT_MAX, den = 0.0f, bsum = 0.0f;
    float4 a0 = make_float4(0.f, 0.f, 0.f, 0.f);
    float4 a1 = make_float4(0.f, 0.f, 0.f, 0.f);
    float4 a2 = make_float4(0.f, 0.f, 0.f, 0.f);
    float4 a3 = make_float4(0.f, 0.f, 0.f, 0.f);

    int j = beg;
    for (; j + 3 < end; j += 4) {
        int2 p0 = g_pack[j],     p1 = g_pack[j + 1];
        int2 p2 = g_pack[j + 2], p3 = g_pack[j + 3];
        // z gathers issued early (independent of m-chain)
        float4 z0 = *(const float4*)&g_z[p0.x * DD + co];
        float4 z1 = *(const float4*)&g_z[p1.x * DD + co];
        float4 z2 = *(const float4*)&g_z[p2.x * DD + co];
        float4 z3 = *(const float4*)&g_z[p3.x * DD + co];
        float aa, e0, e1, e2, e3;
        aa = clamp_inf(g_s[p0.x] + tb); e0 = (aa > 0.f) ? aa : 0.01f * aa;
        aa = clamp_inf(g_s[p1.x] + tb); e1 = (aa > 0.f) ? aa : 0.01f * aa;
        aa = clamp_inf(g_s[p2.x] + tb); e2 = (aa > 0.f) ? aa : 0.01f * aa;
        aa = clamp_inf(g_s[p3.x] + tb); e3 = (aa > 0.f) ? aa : 0.01f * aa;
        float l4 = fmaxf(fmaxf(e0, e1), fmaxf(e2, e3));
        if (l4 > m) {                         // warp-uniform branch
            float f = __expf(m - l4);
            den *= f;
            a0.x *= f; a0.y *= f; a0.z *= f; a0.w *= f;
            a1.x *= f; a1.y *= f; a1.z *= f; a1.w *= f;
            a2.x *= f; a2.y *= f; a2.z *= f; a2.w *= f;
            a3.x *= f; a3.y *= f; a3.z *= f; a3.w *= f;
            m = l4;
        }
        float w0 = __expf(e0 - m), w1 = __expf(e1 - m);
        float w2 = __expf(e2 - m), w3 = __expf(e3 - m);
        den += (w0 + w1) + (w2 + w3);
        float s0 = __int_as_float(p0.y), s1 = __int_as_float(p1.y);
        float s2 = __int_as_float(p2.y), s3 = __int_as_float(p3.y);
        bsum += (s0 + s1) + (s2 + s3);
        float c0 = w0 * s0, c1 = w1 * s1, c2 = w2 * s2, c3 = w3 * s3;
        a0.x += c0 * z0.x; a0.y += c0 * z0.y; a0.z += c0 * z0.z; a0.w += c0 * z0.w;
        a1.x += c1 * z1.x; a1.y += c1 * z1.y; a1.z += c1 * z1.z; a1.w += c1 * z1.w;
        a2.x += c2 * z2.x; a2.y += c2 * z2.y; a2.z += c2 * z2.z; a2.w += c2 * z2.w;
        a3.x += c3 * z3.x; a3.y += c3 * z3.y; a3.z += c3 * z3.z; a3.w += c3 * z3.w;
    }
    for (; j < end; j++) {
        int2 p0 = g_pack[j];
        float4 z0 = *(const float4*)&g_z[p0.x * DD + co];
        float aa = clamp_inf(g_s[p0.x] + tb);
        float e0 = (aa > 0.f) ? aa : 0.01f * aa;
        if (e0 > m) {
            float f = __expf(m - e0);
            den *= f;
            a0.x *= f; a0.y *= f; a0.z *= f; a0.w *= f;
            a1.x *= f; a1.y *= f; a1.z *= f; a1.w *= f;
            a2.x *= f; a2.y *= f; a2.z *= f; a2.w *= f;
            a3.x *= f; a3.y *= f; a3.z *= f; a3.w *= f;
            m = e0;
        }
        float w0 = __expf(e0 - m);
        den += w0;
        float s0 = __int_as_float(p0.y);
        bsum += s0;
        float c0 = w0 * s0;
        a0.x += c0 * z0.x; a0.y += c0 * z0.y; a0.z += c0 * z0.z; a0.w += c0 * z0.w;
    }

    float rc = (den > 0.0f) ? (1.0f / den) * (1.0f / (bsum + 1e-6f)) : 0.0f;
    float4 v;
    v.x = clamp_inf(((a0.x + a1.x) + (a2.x + a3.x)) * rc);
    v.y = clamp_inf(((a0.y + a1.y) + (a2.y + a3.y)) * rc);
    v.z = clamp_inf(((a0.z + a1.z) + (a2.z + a3.z)) * rc);
    v.w = clamp_inf(((a0.w + a1.w) + (a2.w + a3.w)) * rc);
    *(float4*)&g_hnew[node * DD + co] = v;

    atomicAdd(&s_sum[co + 0], v.x); atomicAdd(&s_sq[co + 0], v.x * v.x);
    atomicAdd(&s_sum[co + 1], v.y); atomicAdd(&s_sq[co + 1], v.y * v.y);
    atomicAdd(&s_sum[co + 2], v.z); atomicAdd(&s_sq[co + 2], v.z * v.z);
    atomicAdd(&s_sum[co + 3], v.w); atomicAdd(&s_sq[co + 3], v.w * v.w);

    __syncthreads();
    if (tid < DD) {
        atomicAdd(&g_colsum[tid], s_sum[tid]);
        atomicAdd(&g_colsq[tid], s_sq[tid]);
    }
}

// ---------------- kernel 6: batchnorm + elu (vectorized) ----------------
__global__ void k_bn(float* __restrict__ out, const float* __restrict__ gamma,
                     const float* __restrict__ beta) {
    int i = blockIdx.x * blockDim.x + threadIdx.x;   // float4 index
    if (i >= NN * DD / 4) return;
    int c = (i & 31) * 4;
    const float inv_n = 1.0f / (float)NN;
    float4 cs = *(float4*)&g_colsum[c];
    float4 cq = *(float4*)&g_colsq[c];
    float4 gm = *(const float4*)&gamma[c];
    float4 bt = *(const float4*)&beta[c];
    float4 hv = *(float4*)&g_hnew[i * 4];
    float mu, var, xb;
    float4 o;
    mu = cs.x * inv_n; var = cq.x * inv_n - mu * mu;
    xb = (hv.x - mu) * rsqrtf(var + 1e-5f) * gm.x + bt.x;
    o.x = (xb > 0.0f) ? xb : expm1f(xb);
    mu = cs.y * inv_n; var = cq.y * inv_n - mu * mu;
    xb = (hv.y - mu) * rsqrtf(var + 1e-5f) * gm.y + bt.y;
    o.y = (xb > 0.0f) ? xb : expm1f(xb);
    mu = cs.z * inv_n; var = cq.z * inv_n - mu * mu;
    xb = (hv.z - mu) * rsqrtf(var + 1e-5f) * gm.z + bt.z;
    o.z = (xb > 0.0f) ? xb : expm1f(xb);
    mu = cs.w * inv_n; var = cq.w * inv_n - mu * mu;
    xb = (hv.w - mu) * rsqrtf(var + 1e-5f) * gm.w + bt.w;
    o.w = (xb > 0.0f) ? xb : expm1f(xb);
    *(float4*)&out[i * 4] = o;
}

// ---------------- launcher with fork/join overlap ----------------
extern "C" void kernel_launch(void* const* d_in, const int* in_sizes, int n_in,
                              void* d_out, int out_size) {
    const float* h     = (const float*)d_in[0];
    const int*   src   = (const int*)d_in[1];
    const int*   dst   = (const int*)d_in[2];
    const float* sigma = (const float*)d_in[3];
    const float* fcw   = (const float*)d_in[4];
    const float* fcb   = (const float*)d_in[5];
    const float* attnw = (const float*)d_in[6];
    const float* attnb = (const float*)d_in[7];
    const float* gamma = (const float*)d_in[8];
    const float* beta  = (const float*)d_in[9];
    float* out = (float*)d_out;

    static cudaStream_t s2 = nullptr;
    static cudaEvent_t ev_fork = nullptr, ev_join = nullptr;
    if (s2 == nullptr) {
        cudaStreamCreate(&s2);
        cudaEventCreateWithFlags(&ev_fork, cudaEventDisableTiming);
        cudaEventCreateWithFlags(&ev_join, cudaEventDisableTiming);
    }

    // fork: CSR build on side stream; prep+GEMM on main stream
    cudaEventRecord(ev_fork, 0);
    cudaStreamWaitEvent(s2, ev_fork, 0);
    k_init<<<(NN + 255) / 256, 256, 0, s2>>>();
    k_hist<<<(NE / 4 + 255) / 256, 256, 0, s2>>>(dst);
    k_scan<<<1, 1024, 0, s2>>>();
    k_fill<<<(NE / 4 + 255) / 256, 256, 0, s2>>>(src, dst, sigma);
    cudaEventRecord(ev_join, s2);

    k_prep<<<(NN * 64 + 255) / 256, 256>>>(h);
    k_prepw<<<(128 * 64 + 255) / 256, 256>>>(fcw);
    k_gemm_bf<<<(NN + 127) / 128, 256>>>(fcb, attnw);

    // join
    cudaStreamWaitEvent(0, ev_join, 0);
    k_node<<<NN / 8, 256>>>(attnb);
    k_bn<<<(NN * DD / 4 + 255) / 256, 256>>>(out, gamma, beta);
}